// round 16
// baseline (speedup 1.0000x reference)
#include <cuda_runtime.h>
#include <cooperative_groups.h>

namespace cg = cooperative_groups;

#define BS    64
#define SL    8192
#define EDIM  64
#define DDIM  64
#define VOCAB 1088
#define NVAL  64
#define CSIZE 8                     // cluster size = CTAs per batch
#define SLICE (VOCAB / CSIZE)       // 136 EK rows per CTA
#define CHUNK (SL / CSIZE)          // 1024 elements per CTA
#define EPT   4

// ---------------------------------------------------------------------------
// ONE fused kernel. grid = 512 CTAs = 64 clusters x 8. Cluster = one batch.
// Each CTA: prefetch indices -> redundant Qk GEMV -> own 136-row EK slice in
// SMEM -> cluster.sync -> DSMEM gathers -> DSMEM bin reduce -> rank0 output.
// No device-global scratch, no multi-launch, no software spin barriers.
// ---------------------------------------------------------------------------
__global__ void __cluster_dims__(CSIZE, 1, 1) __launch_bounds__(256)
fused_kernel(
    const int*   __restrict__ x,
    const int*   __restrict__ q,
    const float* __restrict__ embK,
    const float* __restrict__ Wk_w,   // (64, 128) row-major
    const float* __restrict__ Wq_w,   // (64, 64) row-major
    const float* __restrict__ Wq_b,
    float*       __restrict__ out)
{
    cg::cluster_group cluster = cg::this_cluster();
    const int rank = (int)cluster.block_rank();
    const int b    = blockIdx.x / CSIZE;
    const int tid  = threadIdx.x;
    const int warp = tid >> 5;

    __shared__ float EKs [SLICE];       // this CTA's EK slice (rows rank*136..)
    __shared__ float EVs [NVAL];        // rank 0 only
    __shared__ float cbins[NVAL];       // rank 0: cluster-combined bins
    __shared__ float Qks [EDIM];
    __shared__ float Qs  [DDIM];
    __shared__ float eqs [EDIM];
    __shared__ float part[256];
    __shared__ float bins[8][NVAL];     // warp-replicated local histograms

    // ---- 1) Index prefetch: 4MB chip-wide, stays in flight ----
    const int* kp = x + (size_t)b * 2 * SL + rank * CHUNK;
    const int* vp = kp + SL;
    const int4 k4 = __ldg(reinterpret_cast<const int4*>(kp) + tid);
    const int4 w4 = __ldg(reinterpret_cast<const int4*>(vp) + tid);

    // ---- 2) Redundant Qk (R14-proven GEMV; weights prefetched to regs) ----
    const int qi = q[b];
    const int d_q = tid >> 2, s_q = tid & 3;
    float4 wq[4];
    {
        const float4* wrow = reinterpret_cast<const float4*>(
            Wq_w + (size_t)d_q * EDIM + s_q * 16);
        #pragma unroll
        for (int i = 0; i < 4; i++) wq[i] = wrow[i];
    }
    const int c = tid & 127, hh = tid >> 7;
    float wk[32];
    {
        const float* base = Wk_w + (size_t)hh * 32 * 128 + c;
        #pragma unroll
        for (int i = 0; i < 32; i++) wk[i] = base[(size_t)i * 128];
    }
    const float wqb = (tid < DDIM) ? Wq_b[tid] : 0.f;

    // zero local bins + (rank0) cbins while loads fly
    for (int i = tid; i < 8 * NVAL; i += 256) (&bins[0][0])[i] = 0.f;
    if (rank == 0 && tid < NVAL) cbins[tid] = 0.f;

    if (tid < EDIM) eqs[tid] = embK[(size_t)qi * EDIM + tid];
    __syncthreads();

    {   // Q
        float acc = 0.f;
        #pragma unroll
        for (int i = 0; i < 4; i++) {
            const int e = s_q * 16 + i * 4;
            acc += wq[i].x * eqs[e]     + wq[i].y * eqs[e + 1]
                 + wq[i].z * eqs[e + 2] + wq[i].w * eqs[e + 3];
        }
        part[tid] = acc;
    }
    __syncthreads();
    if (tid < DDIM)
        Qs[tid] = part[tid * 4] + part[tid * 4 + 1]
                + part[tid * 4 + 2] + part[tid * 4 + 3] + wqb;
    __syncthreads();

    {   // Qk / SV columns
        float acc = 0.f;
        #pragma unroll
        for (int i = 0; i < 32; i++)
            acc = fmaf(wk[i], Qs[hh * 32 + i], acc);
        part[tid] = acc;
    }
    __syncthreads();
    if (tid < 128) {
        const float val = (part[tid] + part[tid + 128]) * 0.125f;
        if (tid < NVAL) { if (rank == 0) EVs[tid] = __expf(val); }
        else            Qks[tid - NVAL] = val;
    }
    __syncthreads();

    // ---- 3) EK slice: rows [rank*136, +136), dot(embK row, Qk), exp ----
    if (tid < SLICE) {
        const float4* row = reinterpret_cast<const float4*>(
            embK + (size_t)(rank * SLICE + tid) * EDIM);
        float acc = 0.f;
        #pragma unroll
        for (int i = 0; i < 16; i++) {
            const float4 e4 = row[i];
            acc += e4.x * Qks[i * 4] + e4.y * Qks[i * 4 + 1]
                 + e4.z * Qks[i * 4 + 2] + e4.w * Qks[i * 4 + 3];
        }
        EKs[tid] = __expf(acc);
    }
    __syncthreads();

    // ---- 4) HW cluster barrier: all slices + cbins visible ----
    cluster.sync();

    // ---- 5) Gathers via DSMEM + local histogram ----
    {
        const int kk[EPT] = {k4.x, k4.y, k4.z, k4.w};
        const int vv[EPT] = {w4.x - NVAL, w4.y - NVAL, w4.z - NVAL, w4.w - NVAL};
        #pragma unroll
        for (int i = 0; i < EPT; i++) {
            const int key = kk[i];
            const int r   = key / SLICE;          // const-div -> mul/shift
            const int idx = key - r * SLICE;
            const float* rEK = cluster.map_shared_rank(EKs, r);
            atomicAdd(&bins[warp][vv[i]], rEK[idx]);
        }
    }
    __syncthreads();

    // ---- 6) Reduce local bins, DSMEM-accumulate into rank 0 ----
    if (tid < NVAL) {
        float bsum = 0.f;
        #pragma unroll
        for (int w = 0; w < 8; w++) bsum += bins[w][tid];
        float* rcb = cluster.map_shared_rank(cbins, 0);
        atomicAdd(&rcb[tid], bsum);
    }
    cluster.sync();

    // ---- 7) rank 0: apply EV, normalize, write ----
    if (rank == 0) {
        if (tid < NVAL) part[tid] = cbins[tid] * EVs[tid];
        __syncthreads();
        if (tid < 32) {
            float zz = part[tid] + part[tid + 32];
            #pragma unroll
            for (int o = 16; o > 0; o >>= 1)
                zz += __shfl_xor_sync(0xffffffffu, zz, o);
            part[64] = 0.f;                        // placeholder slot
            if (tid == 0) part[64] = __frcp_rn(zz);
        }
        __syncthreads();
        if (tid < NVAL) out[b * NVAL + tid] = part[tid] * part[64];
    }
    // (final cluster.sync not needed: all remote reads/atomics complete before
    //  the second cluster.sync above; rank0 reads only its own shared after.)
}

// ---------------------------------------------------------------------------
// Inputs (metadata order): x(int32), q(int32), embK, Wk_w, Wk_b, Wq_w, Wq_b.
// Wk_b is softmax-invariant (constant per batch) and intentionally unused.
// ---------------------------------------------------------------------------
extern "C" void kernel_launch(void* const* d_in, const int* in_sizes, int n_in,
                              void* d_out, int out_size)
{
    const int*   x    = (const int*)  d_in[0];
    const int*   q    = (const int*)  d_in[1];
    const float* embK = (const float*)d_in[2];
    const float* Wk_w = (const float*)d_in[3];
    const float* Wq_w = (const float*)d_in[5];
    const float* Wq_b = (const float*)d_in[6];
    float* out = (float*)d_out;

    fused_kernel<<<BS * CSIZE, 256>>>(x, q, embK, Wk_w, Wq_w, Wq_b, out);
}

// round 17
// speedup vs baseline: 1.3766x; 1.3766x over previous
#include <cuda_runtime.h>

#define BS    64
#define SL    8192
#define EDIM  64
#define DDIM  64
#define VOCAB 1088
#define NVAL  64
#define NTILE 17
#define SPLIT 8
#define CHUNK (SL / SPLIT)          // 1024
#define EPT   4

// Scratch (no allocations allowed)
__device__ float g_EV[BS * NVAL];
__device__ float g_EK[BS * VOCAB];
__device__ float g_num[BS * NVAL];   // zero-init; reset by combining block
__device__ int   g_cnt[BS];          // zero-init; reset by combining block

// ---------------------------------------------------------------------------
// A: EK + redundant Qk. grid = 64 batches x 17 tiles = 1088 blocks, 128 thr.
// Each block redundantly computes its batch's Qk (lean: shared reductions,
// coalesced weight reads, small reg footprint) then does the R11 tile flow.
// 17x redundancy trades ~35MB of L2-hot weight reads for deleting the 5.8us
// small-grid qk launch. tile==0 blocks also emit EV.
// ---------------------------------------------------------------------------
__global__ __launch_bounds__(128) void ekq_kernel(
    const int*   __restrict__ q,
    const float* __restrict__ embK,
    const float* __restrict__ Wk_w,   // (64, 128) row-major
    const float* __restrict__ Wq_w,   // (64, 64) row-major
    const float* __restrict__ Wq_b)
{
    const int bid  = blockIdx.x;
    const int b    = bid / NTILE;
    const int tile = bid % NTILE;
    const int v0   = tile * 64;
    const int tid  = threadIdx.x;
    const int v    = tid & 63;
    const int h    = tid >> 6;        // d-half / e-half selector

    __shared__ float eqs[EDIM];
    __shared__ float Qs [DDIM];
    __shared__ float qks[EDIM];
    __shared__ float part[128];
    __shared__ float tl[64 * 65];     // padded tile: conflict-free

    const int qi = q[b];              // broadcast LDG, starts the chain

    // Tile load first — independent of the Qk chain, stays in flight
    {
        const float4* src = reinterpret_cast<const float4*>(embK + (size_t)v0 * EDIM);
        for (int i = tid; i < 1024; i += 128) {
            const float4 val = src[i];
            float* d = &tl[(i >> 4) * 65 + (i & 15) * 4];
            d[0] = val.x; d[1] = val.y; d[2] = val.z; d[3] = val.w;
        }
    }
    if (tid < EDIM) eqs[tid] = embK[(size_t)qi * EDIM + tid];
    __syncthreads();

    // Q: thread (d = tid>>1, hq = tid&1) -> 32-wide partial via f4 row loads
    {
        const int d = tid >> 1, hq = tid & 1;
        const float4* wrow = reinterpret_cast<const float4*>(
            Wq_w + (size_t)d * EDIM + hq * 32);
        float acc = 0.f;
        #pragma unroll
        for (int i = 0; i < 8; i++) {
            const float4 w4 = wrow[i];
            const int e = hq * 32 + i * 4;
            acc += w4.x * eqs[e]     + w4.y * eqs[e + 1]
                 + w4.z * eqs[e + 2] + w4.w * eqs[e + 3];
        }
        part[tid] = acc;
    }
    __syncthreads();
    if (tid < DDIM)
        Qs[tid] = part[2 * tid] + part[2 * tid + 1] + Wq_b[tid];
    __syncthreads();

    // Qk: col c = 64+v, d-half h (coalesced Wk column loads across lanes)
    {
        const float* base = Wk_w + (size_t)h * 32 * 128 + 64 + v;
        float acc = 0.f;
        #pragma unroll
        for (int i = 0; i < 32; i++)
            acc = fmaf(base[(size_t)i * 128], Qs[h * 32 + i], acc);
        part[tid] = acc;
    }
    __syncthreads();
    if (tid < EDIM) qks[tid] = (part[tid] + part[tid + 64]) * 0.125f;
    __syncthreads();                  // part free; qks published

    // EV: tile==0 blocks only (block-uniform branch; inner sync is safe)
    if (tile == 0) {
        const float* base = Wk_w + (size_t)h * 32 * 128 + v;
        float acc = 0.f;
        #pragma unroll
        for (int i = 0; i < 32; i++)
            acc = fmaf(base[(size_t)i * 128], Qs[h * 32 + i], acc);
        part[tid] = acc;
        __syncthreads();
        if (tid < NVAL)
            g_EV[b * NVAL + tid] = __expf((part[tid] + part[tid + 64]) * 0.125f);
        __syncthreads();
    }

    // EK tile dot (R11 flow): exp(embK row . Qk), coalesced 256B write
    {
        float acc = 0.f;
        #pragma unroll
        for (int i = 0; i < 32; i++)
            acc = fmaf(tl[v * 65 + h * 32 + i], qks[h * 32 + i], acc);
        part[tid] = acc;
    }
    __syncthreads();
    if (tid < 64)
        g_EK[(size_t)b * VOCAB + v0 + tid] = __expf(part[tid] + part[tid + 64]);
}

// ---------------------------------------------------------------------------
// Kernel B: gather-histogram (byte-identical to R11: measured best).
// grid = 64 batches x 8 splits (512 blocks), 256 threads, 4 elems/thread.
// ---------------------------------------------------------------------------
__global__ __launch_bounds__(256) void attn_kernel(
    const int* __restrict__ x,
    float*     __restrict__ out)
{
    const int b    = blockIdx.x >> 3;
    const int sp   = blockIdx.x & 7;
    const int tid  = threadIdx.x;
    const int warp = tid >> 5;

    __shared__ float EKs[VOCAB];
    __shared__ float bins[8][NVAL];
    __shared__ float num[NVAL];
    __shared__ float rcpZ;
    __shared__ int   lastFlag;

    const int* kp = x + (size_t)b * 2 * SL + sp * CHUNK;
    const int* vp = kp + SL;
    const int4 k4 = __ldg(reinterpret_cast<const int4*>(kp) + tid);
    const int4 w4 = __ldg(reinterpret_cast<const int4*>(vp) + tid);

    {
        const float4* src = reinterpret_cast<const float4*>(g_EK + (size_t)b * VOCAB);
        float4* dst = reinterpret_cast<float4*>(EKs);
        for (int i = tid; i < VOCAB / 4; i += 256) dst[i] = src[i];
    }
    for (int i = tid; i < 8 * NVAL; i += 256) (&bins[0][0])[i] = 0.f;
    __syncthreads();

    const int kk[EPT] = {k4.x, k4.y, k4.z, k4.w};
    const int vv[EPT] = {w4.x - NVAL, w4.y - NVAL, w4.z - NVAL, w4.w - NVAL};

    #pragma unroll
    for (int i = 0; i < EPT; i++)
        atomicAdd(&bins[warp][vv[i]], EKs[kk[i]]);
    __syncthreads();

    if (tid < NVAL) {
        float bsum = 0.f;
        #pragma unroll
        for (int w = 0; w < 8; w++) bsum += bins[w][tid];
        atomicAdd(&g_num[b * NVAL + tid], bsum);
    }
    __syncthreads();

    if (tid == 0) {
        __threadfence();
        const int old = atomicAdd(&g_cnt[b], 1);
        lastFlag = (old == SPLIT - 1) ? 1 : 0;
        __threadfence();
    }
    __syncthreads();

    if (lastFlag) {
        if (tid < NVAL) {
            volatile float* vnum = g_num + b * NVAL;
            num[tid] = vnum[tid] * g_EV[b * NVAL + tid];
        }
        __syncthreads();
        if (tid < 32) {
            float zz = num[tid] + num[tid + 32];
            #pragma unroll
            for (int o = 16; o > 0; o >>= 1) zz += __shfl_xor_sync(0xffffffffu, zz, o);
            if (tid == 0) rcpZ = __frcp_rn(zz);
        }
        __syncthreads();
        if (tid < NVAL) {
            out[b * NVAL + tid] = num[tid] * rcpZ;
            g_num[b * NVAL + tid] = 0.f;            // re-arm accumulator
        }
        __syncthreads();
        if (tid == 0) g_cnt[b] = 0;                 // re-arm counter
    }
}

// ---------------------------------------------------------------------------
// Inputs (metadata order): x(int32), q(int32), embK, Wk_w, Wk_b, Wq_w, Wq_b.
// Wk_b is softmax-invariant (constant per batch) and intentionally unused.
// ---------------------------------------------------------------------------
extern "C" void kernel_launch(void* const* d_in, const int* in_sizes, int n_in,
                              void* d_out, int out_size)
{
    const int*   x    = (const int*)  d_in[0];
    const int*   q    = (const int*)  d_in[1];
    const float* embK = (const float*)d_in[2];
    const float* Wk_w = (const float*)d_in[3];
    const float* Wq_w = (const float*)d_in[5];
    const float* Wq_b = (const float*)d_in[6];
    float* out = (float*)d_out;

    ekq_kernel<<<BS * NTILE, 128>>>(q, embK, Wk_w, Wq_w, Wq_b);
    attn_kernel<<<BS * SPLIT, 256>>>(x, out);
}